// round 5
// baseline (speedup 1.0000x reference)
#include <cuda_runtime.h>
#include <math.h>

// Problem dims
#define BB 256
#define TT 512
#define HH 256
#define G3 768          // 3*H
#define INDIM 75
#define BT (BB*TT)      // 131072

// ---------------- scratch (device globals; no allocations allowed) ---------
__device__ float g_xg[(size_t)BB * TT * G3];     // input-gate preactivations (reused per layer)
__device__ float g_out0[(size_t)BB * TT * HH];   // layer-0 hidden states
__device__ float g_hT[BB * HH];                  // layer-1 final hidden state

__device__ __forceinline__ unsigned f2tf32(float v) {
    unsigned u;
    asm("cvt.rna.tf32.f32 %0, %1;" : "=r"(u) : "f"(v));
    return u;
}

__device__ __forceinline__ void mma_tf32(float c[4], const unsigned a[4], unsigned b0, unsigned b1) {
    asm volatile(
        "mma.sync.aligned.m16n8k8.row.col.f32.tf32.tf32.f32 "
        "{%0,%1,%2,%3}, {%4,%5,%6,%7}, {%8,%9}, {%0,%1,%2,%3};"
        : "+f"(c[0]), "+f"(c[1]), "+f"(c[2]), "+f"(c[3])
        : "r"(a[0]), "r"(a[1]), "r"(a[2]), "r"(a[3]), "r"(b0), "r"(b1));
}

__device__ __forceinline__ unsigned smem_u32(const void* p) {
    unsigned a;
    asm("{ .reg .u64 t; cvta.to.shared.u64 t, %1; cvt.u32.u64 %0, t; }" : "=r"(a) : "l"(p));
    return a;
}

__device__ __forceinline__ unsigned mapa_rank(unsigned addr, unsigned rank) {
    unsigned r;
    asm("mapa.shared::cluster.u32 %0, %1, %2;" : "=r"(r) : "r"(addr), "r"(rank));
    return r;
}

// mbarrier wait (parity), acquire at cluster scope (orders remote st.async data)
#define MB_WAIT_CL(addr, ph) do {                                              \
    unsigned _done;                                                            \
    do {                                                                       \
        asm volatile(                                                          \
            "{\n\t.reg .pred p;\n\t"                                           \
            "mbarrier.try_wait.parity.acquire.cluster.shared::cta.b64 p, [%1], %2;\n\t" \
            "selp.b32 %0, 1, 0, p;\n\t}"                                       \
            : "=r"(_done) : "r"(addr), "r"(ph) : "memory");                    \
    } while (!_done);                                                          \
} while (0)

#define MB_INIT(addr, cnt) \
    asm volatile("mbarrier.init.shared.b64 [%0], %1;" :: "r"(addr), "r"(cnt) : "memory")

#define MB_EXPECT_TX(addr, bytes) \
    asm volatile("mbarrier.arrive.expect_tx.shared.b64 _, [%0], %1;" :: "r"(addr), "r"(bytes) : "memory")

#define MB_ARRIVE_REMOTE(addr) \
    asm volatile("mbarrier.arrive.shared::cluster.b64 _, [%0];" :: "r"(addr) : "memory")

#define ST_ASYNC_V4(dst, a0, a1, a2, a3, mbar)                                 \
    asm volatile("st.async.shared::cluster.mbarrier::complete_tx::bytes.v4.b32 " \
                 "[%0], {%1,%2,%3,%4}, [%5];"                                  \
                 :: "r"(dst), "r"(a0), "r"(a1), "r"(a2), "r"(a3), "r"(mbar)    \
                 : "memory")

// ---------------- TF32 tensor-core GEMM: C = A[M,K] @ W[N,K]^T + bias ------
#define TBM 128
#define TBN 64
#define TBK 16
#define TPAD 20

__global__ __launch_bounds__(256) void tf32_gemm_bias_kernel(
    const float* __restrict__ A, const float* __restrict__ W,
    const float* __restrict__ bias, float* __restrict__ C,
    int M, int N, int K)
{
    __shared__ unsigned As[TBM * TPAD];
    __shared__ unsigned Bs[TBN * TPAD];

    const int tid = threadIdx.x;
    const int wid = tid >> 5, lane = tid & 31;
    const int g = lane >> 2, t = lane & 3;
    const int wm = wid & 3, wn = wid >> 2;
    const int m0 = blockIdx.y * TBM;
    const int n0 = blockIdx.x * TBN;

    float acc[2][4][4];
#pragma unroll
    for (int mt = 0; mt < 2; mt++)
#pragma unroll
        for (int nt = 0; nt < 4; nt++)
#pragma unroll
            for (int i = 0; i < 4; i++) acc[mt][nt][i] = 0.f;

    const int am = tid >> 4;
    const int ak = tid & 15;
    const int bn = tid >> 2;
    const int bk4 = (tid & 3) * 4;

    float ra[8], rb[4];
    const int nk = (K + TBK - 1) / TBK;

    {
#pragma unroll
        for (int i = 0; i < 8; i++) {
            int m = am + i * 16;
            ra[i] = (ak < K) ? __ldg(&A[(size_t)(m0 + m) * K + ak]) : 0.f;
        }
#pragma unroll
        for (int i = 0; i < 4; i++) {
            int k = bk4 + i;
            rb[i] = (k < K) ? __ldg(&W[(size_t)(n0 + bn) * K + k]) : 0.f;
        }
    }

    for (int kt = 0; kt < nk; kt++) {
#pragma unroll
        for (int i = 0; i < 8; i++) As[(am + i * 16) * TPAD + ak] = f2tf32(ra[i]);
#pragma unroll
        for (int i = 0; i < 4; i++) Bs[bn * TPAD + bk4 + i] = f2tf32(rb[i]);
        __syncthreads();

        if (kt + 1 < nk) {
            const int kb = (kt + 1) * TBK;
#pragma unroll
            for (int i = 0; i < 8; i++) {
                int m = am + i * 16;
                ra[i] = (kb + ak < K) ? __ldg(&A[(size_t)(m0 + m) * K + kb + ak]) : 0.f;
            }
#pragma unroll
            for (int i = 0; i < 4; i++) {
                int k = kb + bk4 + i;
                rb[i] = (k < K) ? __ldg(&W[(size_t)(n0 + bn) * K + k]) : 0.f;
            }
        }

#pragma unroll
        for (int ks = 0; ks < 2; ks++) {
            const int k = ks * 8;
            unsigned af[2][4];
#pragma unroll
            for (int mt = 0; mt < 2; mt++) {
                int row = wm * 32 + mt * 16;
                af[mt][0] = As[(row + g) * TPAD + k + t];
                af[mt][1] = As[(row + g + 8) * TPAD + k + t];
                af[mt][2] = As[(row + g) * TPAD + k + t + 4];
                af[mt][3] = As[(row + g + 8) * TPAD + k + t + 4];
            }
#pragma unroll
            for (int nt = 0; nt < 4; nt++) {
                int col = wn * 32 + nt * 8;
                unsigned b0 = Bs[(col + g) * TPAD + k + t];
                unsigned b1 = Bs[(col + g) * TPAD + k + t + 4];
#pragma unroll
                for (int mt = 0; mt < 2; mt++) mma_tf32(acc[mt][nt], af[mt], b0, b1);
            }
        }
        __syncthreads();
    }

#pragma unroll
    for (int mt = 0; mt < 2; mt++) {
#pragma unroll
        for (int nt = 0; nt < 4; nt++) {
            int row = m0 + wm * 32 + mt * 16 + g;
            int col = n0 + wn * 32 + nt * 8 + 2 * t;
            float b0 = bias[col], b1 = bias[col + 1];
            C[(size_t)row * N + col]           = acc[mt][nt][0] + b0;
            C[(size_t)row * N + col + 1]       = acc[mt][nt][1] + b1;
            C[(size_t)(row + 8) * N + col]     = acc[mt][nt][2] + b0;
            C[(size_t)(row + 8) * N + col + 1] = acc[mt][nt][3] + b1;
        }
    }
}

// ---------------- fp32 GEMM (tiny FC) --------------------------------------
#define GBM 128
#define GBN 64
#define GBK 8
__global__ __launch_bounds__(256) void gemm_bias_kernel(
    const float* __restrict__ A, const float* __restrict__ W,
    const float* __restrict__ bias, float* __restrict__ C,
    int M, int N, int K)
{
    __shared__ float As[GBK][GBM];
    __shared__ float Bs[GBK][GBN + 4];

    int tid = threadIdx.x;
    int tx = tid & 15;
    int ty = tid >> 4;
    int m0 = blockIdx.x * GBM;
    int n0 = blockIdx.y * GBN;

    float acc[8][4];
#pragma unroll
    for (int i = 0; i < 8; i++)
#pragma unroll
        for (int j = 0; j < 4; j++) acc[i][j] = 0.f;

    for (int k0 = 0; k0 < K; k0 += GBK) {
#pragma unroll
        for (int i = 0; i < 4; i++) {
            int idx = tid + i * 256;
            int m = idx >> 3, kk = idx & 7;
            float v = (k0 + kk < K) ? A[(size_t)(m0 + m) * K + k0 + kk] : 0.f;
            As[kk][m] = v;
        }
#pragma unroll
        for (int i = 0; i < 2; i++) {
            int idx = tid + i * 256;
            int n = idx >> 3, kk = idx & 7;
            float v = (k0 + kk < K) ? W[(size_t)(n0 + n) * K + k0 + kk] : 0.f;
            Bs[kk][n] = v;
        }
        __syncthreads();
#pragma unroll
        for (int kk = 0; kk < GBK; kk++) {
            float a[8], b[4];
#pragma unroll
            for (int i = 0; i < 8; i++) a[i] = As[kk][ty * 8 + i];
#pragma unroll
            for (int j = 0; j < 4; j++) b[j] = Bs[kk][tx * 4 + j];
#pragma unroll
            for (int i = 0; i < 8; i++)
#pragma unroll
                for (int j = 0; j < 4; j++) acc[i][j] = fmaf(a[i], b[j], acc[i][j]);
        }
        __syncthreads();
    }

    float bb[4];
#pragma unroll
    for (int j = 0; j < 4; j++) bb[j] = bias[n0 + tx * 4 + j];
#pragma unroll
    for (int i = 0; i < 8; i++) {
        size_t row = (size_t)(m0 + ty * 8 + i) * N + n0 + tx * 4;
#pragma unroll
        for (int j = 0; j < 4; j++) C[row + j] = acc[i][j] + bb[j];
    }
}

// ---------------- pipelined cluster GRU recurrence -------------------------
// 16 clusters x 8 CTAs; CTA = 32 units (96 gate rows) x 16 batches.
// Per step: mma on local smem h (double-buffered), epilogue pushes tf32 h via
// st.async with mbarrier complete_tx (full barriers), empty barriers gate
// overwrite. CTAs may drift by 1 step -> jitter absorbed, no cluster.sync.
// xg prefetched one full step ahead. h_prev fp32 carried in registers.
#define CL 8
#define RT_THREADS 192
#define RT_GRID 128
#define HP 260          // hs_tf row stride (words): banks 4g+t -> conflict-free
#define DSP 17          // Ds row stride (reader conflict-free)
#define FULL_TX 16384   // 8 CTAs * 128 threads * 16B per step per buffer

__global__ __launch_bounds__(RT_THREADS, 1) __cluster_dims__(CL, 1, 1)
void gru_rec_pipe_kernel(
    const float* __restrict__ W_hh, const float* __restrict__ b_hh, int layer0)
{
    __shared__ unsigned hs_tf[2][16 * HP];      // h (tf32) [b][unit], ping-pong
    __shared__ float    Ds[96 * DSP];           // mma accums [gate-row][b]
    __shared__ unsigned long long mb[4];        // fm0, fm1, em0, em1

    const int tid = threadIdx.x;
    const int wid = tid >> 5;             // 0..5
    const int lane = tid & 31;
    const int g = lane >> 2, t = lane & 3;

    unsigned rank;
    asm("mov.u32 %0, %%cluster_ctarank;" : "=r"(rank));
    const int bg = blockIdx.x >> 3;       // batch group 0..15
    const int j0 = (int)rank * 32;        // this CTA's unit base
    const int b0 = bg * 16;

    // ---- preload static A fragments (W_hh slice) into registers ----
    const int gate_w = wid >> 1;
    const int wrow = gate_w * HH + j0 + (wid & 1) * 16;
    unsigned a[32][4];
#pragma unroll
    for (int ks = 0; ks < 32; ks++) {
        int k = ks * 8;
        a[ks][0] = f2tf32(__ldg(&W_hh[(size_t)(wrow + g) * HH + k + t]));
        a[ks][1] = f2tf32(__ldg(&W_hh[(size_t)(wrow + g + 8) * HH + k + t]));
        a[ks][2] = f2tf32(__ldg(&W_hh[(size_t)(wrow + g) * HH + k + t + 4]));
        a[ks][3] = f2tf32(__ldg(&W_hh[(size_t)(wrow + g + 8) * HH + k + t + 4]));
    }

    // ---- epilogue assignment: thread (eb, ju4) owns units ju4*4..+3, batch eb
    const int eb = (tid & 127) >> 3;      // 0..15
    const int ju4 = tid & 7;              // 0..7
    float bhr[4], bhz[4], bhn[4];
    if (tid < 128) {
#pragma unroll
        for (int i = 0; i < 4; i++) {
            int j = j0 + ju4 * 4 + i;
            bhr[i] = __ldg(&b_hh[j]);
            bhz[i] = __ldg(&b_hh[HH + j]);
            bhn[i] = __ldg(&b_hh[2 * HH + j]);
        }
    }

    // ---- barrier + remote address setup ----
    const unsigned mb0 = smem_u32(&mb[0]);     // fm0=+0, fm1=+8, em0=+16, em1=+24
    if (tid == 0) {
        MB_INIT(mb0 + 0, 1);
        MB_INIT(mb0 + 8, 1);
        MB_INIT(mb0 + 16, CL);
        MB_INIT(mb0 + 24, CL);
    }

    unsigned dst0[CL], mbR[CL];
    unsigned buf_delta = 0;
    {
        unsigned l0 = smem_u32(&hs_tf[0][eb * HP + j0 + ju4 * 4]);
        unsigned l1 = smem_u32(&hs_tf[1][eb * HP + j0 + ju4 * 4]);
        buf_delta = l1 - l0;
#pragma unroll
        for (int r = 0; r < CL; r++) {
            dst0[r] = mapa_rank(l0, (unsigned)r);
            mbR[r]  = mapa_rank(mb0, (unsigned)r);
        }
    }

    // ---- zero-init buffer 0 (step 0 reads local zeros, no barrier) ----
    for (int idx = tid; idx < 16 * HP; idx += RT_THREADS)
        hs_tf[0][idx] = 0u;
    __syncthreads();
    asm volatile("barrier.cluster.arrive.aligned;" ::: "memory");
    asm volatile("barrier.cluster.wait.aligned;" ::: "memory");

    // ---- fp32 h_prev carried in registers ----
    float hprev[4] = {0.f, 0.f, 0.f, 0.f};

    // ---- preload xg for step 0 ----
    float4 xr_c, xz_c, xn_c;
    if (tid < 128) {
        const float* xgp = &g_xg[((size_t)(b0 + eb) * TT) * G3 + j0 + ju4 * 4];
        xr_c = __ldcg((const float4*)&xgp[0]);
        xz_c = __ldcg((const float4*)&xgp[HH]);
        xn_c = __ldcg((const float4*)&xgp[2 * HH]);
    }

    for (int s = 0; s < TT; s++) {
        const int cur = s & 1;
        const int nxt = cur ^ 1;
        const unsigned par = ((unsigned)(s - 1) >> 1) & 1u;  // valid for s>=1

        // ---- prefetch xg for s+1 (hidden under this whole step) ----
        float4 xr_n, xz_n, xn_n;
        if (tid < 128 && s + 1 < TT) {
            const float* xgp = &g_xg[((size_t)(b0 + eb) * TT + (s + 1)) * G3 + j0 + ju4 * 4];
            xr_n = __ldcg((const float4*)&xgp[0]);
            xz_n = __ldcg((const float4*)&xgp[HH]);
            xn_n = __ldcg((const float4*)&xgp[2 * HH]);
        }

        // ---- wait for full h buffer (remote pushes from step s-1) ----
        if (s > 0) MB_WAIT_CL(mb0 + cur * 8, par);

        // ---- prime next full-phase (expect_tx for buffer nxt) ----
        if (tid == 0 && s + 1 < TT) MB_EXPECT_TX(mb0 + nxt * 8, FULL_TX);

        // ---- tensor-core matmul: D[96 x 16] = W_slice @ h^T ----
        const unsigned* hb = hs_tf[cur];
        float c0[4] = {0.f, 0.f, 0.f, 0.f};
        float c1[4] = {0.f, 0.f, 0.f, 0.f};
#pragma unroll
        for (int ks = 0; ks < 32; ks++) {
            int k = ks * 8;
            unsigned b00 = hb[g * HP + k + t];
            unsigned b01 = hb[g * HP + k + t + 4];
            unsigned b10 = hb[(8 + g) * HP + k + t];
            unsigned b11 = hb[(8 + g) * HP + k + t + 4];
            mma_tf32(c0, a[ks], b00, b01);
            mma_tf32(c1, a[ks], b10, b11);
        }
        {
            int lr = wid * 16 + g;
            Ds[lr * DSP + 2 * t]           = c0[0];
            Ds[lr * DSP + 2 * t + 1]       = c0[1];
            Ds[(lr + 8) * DSP + 2 * t]     = c0[2];
            Ds[(lr + 8) * DSP + 2 * t + 1] = c0[3];
            Ds[lr * DSP + 8 + 2 * t]           = c1[0];
            Ds[lr * DSP + 8 + 2 * t + 1]       = c1[1];
            Ds[(lr + 8) * DSP + 8 + 2 * t]     = c1[2];
            Ds[(lr + 8) * DSP + 8 + 2 * t + 1] = c1[3];
        }
        __syncthreads();

        // ---- signal "done reading buffer cur" to all cluster CTAs ----
        if (tid == 0 && s + 1 < TT) {
#pragma unroll
            for (int r = 0; r < CL; r++)
                MB_ARRIVE_REMOTE(mbR[r] + 16 + cur * 8);
        }

        // ---- gates + state update ----
        if (tid < 128) {
            float hnew[4];
#pragma unroll
            for (int i = 0; i < 4; i++) {
                int jl = ju4 * 4 + i;
                float xr = (i == 0) ? xr_c.x : (i == 1) ? xr_c.y : (i == 2) ? xr_c.z : xr_c.w;
                float xz = (i == 0) ? xz_c.x : (i == 1) ? xz_c.y : (i == 2) ? xz_c.z : xz_c.w;
                float xn = (i == 0) ? xn_c.x : (i == 1) ? xn_c.y : (i == 2) ? xn_c.z : xn_c.w;
                float pr = Ds[jl * DSP + eb];
                float pz = Ds[(32 + jl) * DSP + eb];
                float pn = Ds[(64 + jl) * DSP + eb];
                // sigmoid/tanh via fast exp (error << tf32 rounding)
                float er = __expf(-(xr + bhr[i] + pr));
                float ez = __expf(-(xz + bhz[i] + pz));
                float r = 1.f / (1.f + er);
                float z = 1.f / (1.f + ez);
                float targ = xn + r * (bhn[i] + pn);
                float e2 = __expf(2.f * targ);
                float nn = 1.f - 2.f / (e2 + 1.f);   // tanh
                hnew[i] = (1.f - z) * nn + z * hprev[i];
                hprev[i] = hnew[i];
            }

            // ---- producer: wait empty(nxt), then push tf32 h to cluster ----
            if (s + 1 < TT) {
                if (s > 0) MB_WAIT_CL(mb0 + 16 + nxt * 8, par);
                unsigned u0 = f2tf32(hnew[0]), u1 = f2tf32(hnew[1]);
                unsigned u2 = f2tf32(hnew[2]), u3 = f2tf32(hnew[3]);
                unsigned bofs = nxt ? buf_delta : 0u;
#pragma unroll
                for (int rr = 0; rr < CL; rr++) {
                    int r = (rr + (tid & 7)) & (CL - 1);
                    ST_ASYNC_V4(dst0[r] + bofs, u0, u1, u2, u3, mbR[r] + nxt * 8);
                }
            }

            // ---- global stores (off critical path) ----
            if (layer0) {
                float4 hv = make_float4(hnew[0], hnew[1], hnew[2], hnew[3]);
                *(float4*)&g_out0[((size_t)(b0 + eb) * TT + s) * HH + j0 + ju4 * 4] = hv;
            } else if (s == TT - 1) {
                float4 hv = make_float4(hnew[0], hnew[1], hnew[2], hnew[3]);
                *(float4*)&g_hT[(size_t)(b0 + eb) * HH + j0 + ju4 * 4] = hv;
            }

            // rotate prefetched xg
            xr_c = xr_n; xz_c = xz_n; xn_c = xn_n;
        }
    }

    // no in-flight remote ops (last step skipped all); safety sync before exit
    asm volatile("barrier.cluster.arrive.aligned;" ::: "memory");
    asm volatile("barrier.cluster.wait.aligned;" ::: "memory");
}

// ---------------------------------------------------------------------------
extern "C" void kernel_launch(void* const* d_in, const int* in_sizes, int n_in,
                              void* d_out, int out_size)
{
    const float* x     = (const float*)d_in[0];
    const float* W_ih0 = (const float*)d_in[1];
    const float* W_hh0 = (const float*)d_in[2];
    const float* b_ih0 = (const float*)d_in[3];
    const float* b_hh0 = (const float*)d_in[4];
    const float* W_ih1 = (const float*)d_in[5];
    const float* W_hh1 = (const float*)d_in[6];
    const float* b_ih1 = (const float*)d_in[7];
    const float* b_hh1 = (const float*)d_in[8];
    const float* fc_W  = (const float*)d_in[9];
    const float* fc_b  = (const float*)d_in[10];
    float* out = (float*)d_out;

    float *xg, *out0, *hT;
    cudaGetSymbolAddress((void**)&xg,   g_xg);
    cudaGetSymbolAddress((void**)&out0, g_out0);
    cudaGetSymbolAddress((void**)&hT,   g_hT);

    // layer 0 input preactivations: [BT,75] @ [768,75]^T   (TF32 tensor cores)
    tf32_gemm_bias_kernel<<<dim3(G3 / TBN, BT / TBM), 256>>>(x, W_ih0, b_ih0, xg, BT, G3, INDIM);
    // layer 0 recurrence -> g_out0 (pipelined cluster)
    gru_rec_pipe_kernel<<<RT_GRID, RT_THREADS>>>(W_hh0, b_hh0, 1);
    // layer 1 input preactivations: [BT,256] @ [768,256]^T (TF32 tensor cores)
    tf32_gemm_bias_kernel<<<dim3(G3 / TBN, BT / TBM), 256>>>(out0, W_ih1, b_ih1, xg, BT, G3, HH);
    // layer 1 recurrence -> g_hT
    gru_rec_pipe_kernel<<<RT_GRID, RT_THREADS>>>(W_hh1, b_hh1, 0);
    // FC: [256,256] @ [256,256]^T + b (fp32, tiny)
    gemm_bias_kernel<<<dim3(BB / GBM, HH / GBN), 256>>>(hT, fc_W, fc_b, out, BB, HH, HH);
}